// round 2
// baseline (speedup 1.0000x reference)
#include <cuda_runtime.h>

#define BB 512
#define DD 1024
#define HH 512
#define CC 4
#define DCH 16              // d-chunk size (keeps P scratch L2-resident: 67MB)
#define KK (DD / DCH)       // 64 chunks

// P[k][h][b] : prefix of (c + sum_{j<k*DCH} x[b,j]*W[h,j])
__device__ float g_P[(size_t)KK * HH * BB];   // 67 MB scratch

__device__ __forceinline__ float sigmoid_tanh(float a) {
    float th;
    asm("tanh.approx.f32 %0, %1;" : "=f"(th) : "f"(a * 0.5f));  // 1 MUFU
    return fmaf(0.5f, th, 0.5f);
}
__device__ __forceinline__ unsigned long long pack2(float lo, float hi) {
    unsigned long long r;
    asm("mov.b64 %0, {%1, %2};" : "=l"(r) : "f"(lo), "f"(hi));
    return r;
}
__device__ __forceinline__ void fma2(unsigned long long& d,
                                     unsigned long long a, unsigned long long b) {
    asm("fma.rn.f32x2 %0, %1, %2, %0;" : "+l"(d) : "l"(a), "l"(b));
}
__device__ __forceinline__ void unpack2(unsigned long long v, float& lo, float& hi) {
    asm("mov.b64 {%0, %1}, %2;" : "=f"(lo), "=f"(hi) : "l"(v));
}

// ---------------- Phase 1: chunked prefix GEMM (LDG-only, no smem) ----------------
// grid (HH/16, BB/64), block 256. Thread: bl = tid&63, hg = tid>>6 -> 4 contiguous h.
__global__ __launch_bounds__(256) void nade_phase1(
    const float* __restrict__ x, const float* __restrict__ W,
    const float* __restrict__ cvec)
{
    const int h0 = blockIdx.x * 16;
    const int b0 = blockIdx.y * 64;
    const int tid = threadIdx.x;
    const int bl = tid & 63;
    const int hg = tid >> 6;            // 0..3
    const int hbase = h0 + hg * 4;
    const int b = b0 + bl;

    float acc[4];
#pragma unroll
    for (int m = 0; m < 4; m++) acc[m] = __ldg(&cvec[hbase + m]);

    const float4* xr = (const float4*)(x + (size_t)b * DD);

    for (int k = 0; k < KK; k++) {
        // write exclusive prefix for chunk k
        float* Pk = g_P + (size_t)k * HH * BB;
#pragma unroll
        for (int m = 0; m < 4; m++)
            Pk[(size_t)(hbase + m) * BB + b] = acc[m];

        float xv[DCH];
#pragma unroll
        for (int q = 0; q < 4; q++) {
            float4 v = __ldg(&xr[k * 4 + q]);
            xv[4 * q + 0] = v.x; xv[4 * q + 1] = v.y;
            xv[4 * q + 2] = v.z; xv[4 * q + 3] = v.w;
        }
#pragma unroll
        for (int m = 0; m < 4; m++) {
            const float4* wr = (const float4*)(W + (size_t)(hbase + m) * DD) + k * 4;
#pragma unroll
            for (int q = 0; q < 4; q++) {
                float4 w = __ldg(&wr[q]);
                acc[m] = fmaf(xv[4 * q + 0], w.x, acc[m]);
                acc[m] = fmaf(xv[4 * q + 1], w.y, acc[m]);
                acc[m] = fmaf(xv[4 * q + 2], w.z, acc[m]);
                acc[m] = fmaf(xv[4 * q + 3], w.w, acc[m]);
            }
        }
    }
}

// ---------------- Phase 2: per-chunk sequential NADE ----------------
// grid (KK, BB/64), block 256: tid -> bl = tid&63, grp = tid>>6:
//   hseg = grp&1 (H half), dsub = grp>>1 (d-subchunk of 8).
// dsub1 advances a through d0..7 (8 FMAs) then does full work on d8..15.
__global__ __launch_bounds__(256, 3) void nade_phase2(
    const float* __restrict__ x, const float* __restrict__ V,
    const float* __restrict__ bias, const float* __restrict__ W,
    float* __restrict__ out)
{
    __shared__ float red[DCH * CC][64];   // 16 KB, conflict-free

    const int k = blockIdx.x;
    const int b0 = blockIdx.y * 64;
    const int tid = threadIdx.x;
    const int bl = tid & 63;
    const int grp = tid >> 6;
    const int hseg = grp & 1;
    const int dsub = grp >> 1;            // 0 or 1
    const int b = b0 + bl;
    const int d0 = k * DCH;
    const int dbase = d0 + dsub * 8;

    // preload x[b, d0:d0+16] (dsub0 only uses first 8, dsub1 uses all 16)
    float xv[DCH];
    {
        const float4* xr = (const float4*)(x + (size_t)b * DD + d0);
#pragma unroll
        for (int q = 0; q < 4; q++) {
            float4 v = __ldg(&xr[q]);
            xv[4 * q + 0] = v.x; xv[4 * q + 1] = v.y;
            xv[4 * q + 2] = v.z; xv[4 * q + 3] = v.w;
        }
    }

    unsigned long long acc2[8][2];        // 8 d × 4 c, packed f32x2
#pragma unroll
    for (int d = 0; d < 8; d++) { acc2[d][0] = 0ull; acc2[d][1] = 0ull; }

    const float* Pk = g_P + (size_t)k * HH * BB;
    const int hstart = hseg * (HH / 2);
    const float* xsub = xv + dsub * 8;

    for (int h = hstart; h < hstart + HH / 2; h++) {
        float a = __ldg(&Pk[(size_t)h * BB + b]);                 // coalesced over b
        const float* wrow = W + (size_t)h * DD + d0;

        if (dsub == 1) {   // uniform per warp, no divergence
#pragma unroll
            for (int q = 0; q < 2; q++) {
                float4 w = __ldg((const float4*)wrow + q);
                a = fmaf(xv[4 * q + 0], w.x, a);
                a = fmaf(xv[4 * q + 1], w.y, a);
                a = fmaf(xv[4 * q + 2], w.z, a);
                a = fmaf(xv[4 * q + 3], w.w, a);
            }
        }

        const float4* wsub = (const float4*)(wrow + dsub * 8);
        const ulonglong2* vr = (const ulonglong2*)(V + ((size_t)h * DD + dbase) * CC);
#pragma unroll
        for (int q = 0; q < 2; q++) {
            float4 w4 = __ldg(&wsub[q]);
            float wq[4] = {w4.x, w4.y, w4.z, w4.w};
#pragma unroll
            for (int r = 0; r < 4; r++) {
                const int d = 4 * q + r;
                ulonglong2 v = __ldg(&vr[d]);                     // broadcast in warp
                float hv = sigmoid_tanh(a);
                unsigned long long h2 = pack2(hv, hv);
                fma2(acc2[d][0], v.x, h2);
                fma2(acc2[d][1], v.y, h2);
                a = fmaf(xsub[d], wq[r], a);                      // prefix advance
            }
        }
    }

    // combine H-segment partials (once per chunk)
    if (hseg == 1) {
#pragma unroll
        for (int d = 0; d < 8; d++) {
            float l0, l1, l2, l3;
            unpack2(acc2[d][0], l0, l1);
            unpack2(acc2[d][1], l2, l3);
            const int dg = dsub * 8 + d;
            red[dg * CC + 0][bl] = l0;
            red[dg * CC + 1][bl] = l1;
            red[dg * CC + 2][bl] = l2;
            red[dg * CC + 3][bl] = l3;
        }
    }
    __syncthreads();

    if (hseg == 0) {
        float* yout = out + (size_t)b * (DD * CC) + (size_t)dbase * CC;
        float* pout = yout + (size_t)BB * DD * CC;
#pragma unroll
        for (int d = 0; d < 8; d++) {
            const int dg = dsub * 8 + d;
            float l[4];
            unpack2(acc2[d][0], l[0], l[1]);
            unpack2(acc2[d][1], l[2], l[3]);
#pragma unroll
            for (int c = 0; c < CC; c++)
                l[c] += red[dg * CC + c][bl] + __ldg(&bias[(d0 + dg) * CC + c]);

            *(float4*)(yout + d * CC) = make_float4(l[0], l[1], l[2], l[3]);

            float m = fmaxf(fmaxf(l[0], l[1]), fmaxf(l[2], l[3]));
            float s = __expf(l[0] - m) + __expf(l[1] - m) +
                      __expf(l[2] - m) + __expf(l[3] - m);
            float lse = m + __logf(s);
            *(float4*)(pout + d * CC) =
                make_float4(l[0] - lse, l[1] - lse, l[2] - lse, l[3] - lse);
        }
    }
}

extern "C" void kernel_launch(void* const* d_in, const int* in_sizes, int n_in,
                              void* d_out, int out_size) {
    const float* x    = (const float*)d_in[0];
    const float* V    = (const float*)d_in[1];
    const float* bias = (const float*)d_in[2];
    const float* W    = (const float*)d_in[3];
    const float* cvec = (const float*)d_in[4];
    float* out = (float*)d_out;

    nade_phase1<<<dim3(HH / 16, BB / 64), 256>>>(x, W, cvec);
    nade_phase2<<<dim3(KK, BB / 64), 256>>>(x, V, bias, W, out);
}

// round 3
// speedup vs baseline: 1.0848x; 1.0848x over previous
#include <cuda_runtime.h>

#define BB 512
#define DD 1024
#define HH 512
#define CC 4
#define DCH 16              // d-chunk size (keeps P scratch L2-resident: 67MB)
#define KK (DD / DCH)       // 64 chunks

// P[k][h][b] : prefix of (c + sum_{j<k*DCH} x[b,j]*W[h,j])
__device__ float g_P[(size_t)KK * HH * BB];   // 67 MB scratch

__device__ __forceinline__ float sigmoid_tanh(float a) {
    float th;
    asm("tanh.approx.f32 %0, %1;" : "=f"(th) : "f"(a * 0.5f));  // 1 MUFU
    return fmaf(0.5f, th, 0.5f);
}

// ---------------- Phase 1: chunked prefix GEMM (LDG-only) ----------------
// grid (HH/16, BB/64), block 256. Thread: bl = tid&63, hg = tid>>6 -> 4 contiguous h.
__global__ __launch_bounds__(256) void nade_phase1(
    const float* __restrict__ x, const float* __restrict__ W,
    const float* __restrict__ cvec)
{
    const int h0 = blockIdx.x * 16;
    const int b0 = blockIdx.y * 64;
    const int tid = threadIdx.x;
    const int bl = tid & 63;
    const int hg = tid >> 6;            // 0..3
    const int hbase = h0 + hg * 4;
    const int b = b0 + bl;

    float acc[4];
#pragma unroll
    for (int m = 0; m < 4; m++) acc[m] = __ldg(&cvec[hbase + m]);

    const float4* xr = (const float4*)(x + (size_t)b * DD);

    for (int k = 0; k < KK; k++) {
        float* Pk = g_P + (size_t)k * HH * BB;
#pragma unroll
        for (int m = 0; m < 4; m++)
            Pk[(size_t)(hbase + m) * BB + b] = acc[m];

        float xv[DCH];
#pragma unroll
        for (int q = 0; q < 4; q++) {
            float4 v = __ldg(&xr[k * 4 + q]);
            xv[4 * q + 0] = v.x; xv[4 * q + 1] = v.y;
            xv[4 * q + 2] = v.z; xv[4 * q + 3] = v.w;
        }
#pragma unroll
        for (int m = 0; m < 4; m++) {
            const float4* wr = (const float4*)(W + (size_t)(hbase + m) * DD) + k * 4;
#pragma unroll
            for (int q = 0; q < 4; q++) {
                float4 w = __ldg(&wr[q]);
                acc[m] = fmaf(xv[4 * q + 0], w.x, acc[m]);
                acc[m] = fmaf(xv[4 * q + 1], w.y, acc[m]);
                acc[m] = fmaf(xv[4 * q + 2], w.z, acc[m]);
                acc[m] = fmaf(xv[4 * q + 3], w.w, acc[m]);
            }
        }
    }
}

// ---------------- Phase 2: per-chunk sequential NADE ----------------
// grid (KK, BB/32), block 128 = 4 warps. Warp wid: hseg = wid&1, dsub = wid>>1.
// Lanes = 32 consecutive b. dsub1 advances a through d0..7, works on d8..15.
__global__ __launch_bounds__(128, 6) void nade_phase2(
    const float* __restrict__ x, const float* __restrict__ V,
    const float* __restrict__ bias, const float* __restrict__ W,
    float* __restrict__ out)
{
    __shared__ float red[DCH * CC][32];   // 8 KB, conflict-free

    const int k = blockIdx.x;
    const int b0 = blockIdx.y * 32;
    const int tid = threadIdx.x;
    const int bl = tid & 31;
    const int wid = tid >> 5;
    const int hseg = wid & 1;
    const int dsub = wid >> 1;            // 0 or 1
    const int b = b0 + bl;
    const int d0 = k * DCH;
    const int dbase = d0 + dsub * 8;

    // preload x[b, d0:d0+16]
    float xv[DCH];
    {
        const float4* xr = (const float4*)(x + (size_t)b * DD + d0);
#pragma unroll
        for (int q = 0; q < 4; q++) {
            float4 v = __ldg(&xr[q]);
            xv[4 * q + 0] = v.x; xv[4 * q + 1] = v.y;
            xv[4 * q + 2] = v.z; xv[4 * q + 3] = v.w;
        }
    }

    float acc[8][CC];
#pragma unroll
    for (int d = 0; d < 8; d++)
#pragma unroll
        for (int c = 0; c < CC; c++) acc[d][c] = 0.0f;

    const float* Pk = g_P + (size_t)k * HH * BB;
    const int hstart = hseg * (HH / 2);
    const float* xsub = xv + dsub * 8;

    for (int h = hstart; h < hstart + HH / 2; h++) {
        float a = __ldg(&Pk[(size_t)h * BB + b]);                 // coalesced over b
        const float* wrow = W + (size_t)h * DD + d0;

        if (dsub == 1) {   // warp-uniform branch
#pragma unroll
            for (int q = 0; q < 2; q++) {
                float4 w = __ldg((const float4*)wrow + q);
                a = fmaf(xv[4 * q + 0], w.x, a);
                a = fmaf(xv[4 * q + 1], w.y, a);
                a = fmaf(xv[4 * q + 2], w.z, a);
                a = fmaf(xv[4 * q + 3], w.w, a);
            }
        }

        const float4* wsub = (const float4*)(wrow + dsub * 8);
        const float4* vr = (const float4*)(V + ((size_t)h * DD + dbase) * CC);
#pragma unroll
        for (int q = 0; q < 2; q++) {
            float4 w4 = __ldg(&wsub[q]);
            float wq[4] = {w4.x, w4.y, w4.z, w4.w};
#pragma unroll
            for (int r = 0; r < 4; r++) {
                const int d = 4 * q + r;
                float4 v = __ldg(&vr[d]);                         // broadcast in warp
                float hv = sigmoid_tanh(a);
                acc[d][0] = fmaf(hv, v.x, acc[d][0]);
                acc[d][1] = fmaf(hv, v.y, acc[d][1]);
                acc[d][2] = fmaf(hv, v.z, acc[d][2]);
                acc[d][3] = fmaf(hv, v.w, acc[d][3]);
                a = fmaf(xsub[d], wq[r], a);                      // prefix advance
            }
        }
    }

    // combine H-segment partials (once per chunk)
    if (hseg == 1) {
#pragma unroll
        for (int d = 0; d < 8; d++) {
            const int dg = dsub * 8 + d;
#pragma unroll
            for (int c = 0; c < CC; c++)
                red[dg * CC + c][bl] = acc[d][c];
        }
    }
    __syncthreads();

    if (hseg == 0) {
        float* yout = out + (size_t)b * (DD * CC) + (size_t)dbase * CC;
        float* pout = yout + (size_t)BB * DD * CC;
#pragma unroll
        for (int d = 0; d < 8; d++) {
            const int dg = dsub * 8 + d;
            float4 bi = __ldg((const float4*)(bias + (size_t)(d0 + dg) * CC));
            float l[4];
            l[0] = acc[d][0] + red[dg * CC + 0][bl] + bi.x;
            l[1] = acc[d][1] + red[dg * CC + 1][bl] + bi.y;
            l[2] = acc[d][2] + red[dg * CC + 2][bl] + bi.z;
            l[3] = acc[d][3] + red[dg * CC + 3][bl] + bi.w;

            *(float4*)(yout + d * CC) = make_float4(l[0], l[1], l[2], l[3]);

            float m = fmaxf(fmaxf(l[0], l[1]), fmaxf(l[2], l[3]));
            float s = __expf(l[0] - m) + __expf(l[1] - m) +
                      __expf(l[2] - m) + __expf(l[3] - m);
            float lse = m + __logf(s);
            *(float4*)(pout + d * CC) =
                make_float4(l[0] - lse, l[1] - lse, l[2] - lse, l[3] - lse);
        }
    }
}

extern "C" void kernel_launch(void* const* d_in, const int* in_sizes, int n_in,
                              void* d_out, int out_size) {
    const float* x    = (const float*)d_in[0];
    const float* V    = (const float*)d_in[1];
    const float* bias = (const float*)d_in[2];
    const float* W    = (const float*)d_in[3];
    const float* cvec = (const float*)d_in[4];
    float* out = (float*)d_out;

    nade_phase1<<<dim3(HH / 16, BB / 64), 256>>>(x, W, cvec);
    nade_phase2<<<dim3(KK, BB / 32), 128>>>(x, V, bias, W, out);
}

// round 4
// speedup vs baseline: 1.4635x; 1.3491x over previous
#include <cuda_runtime.h>

#define BB 512
#define DD 1024
#define HH 512
#define CC 4
#define DCH 16
#define KK (DD / DCH)       // 64 chunks
#define HITER (HH / 2)      // 256 per hseg

// P'[k][h][b] = 0.5*(c + sum_{j<16k} x[b,j]W[h,j]); +BB pad for prefetch overrun
__device__ float g_P[((size_t)KK * HH + 1) * BB];
// xT[d][b] = 0.5 * x[b][d]
__device__ float g_XT[(size_t)DD * BB];
// vb[d][c] = bias[d][c] + 0.5 * sum_h V[h][d][c]
__device__ float g_VB[DD * CC];

__device__ __forceinline__ float tanh_fast(float a) {
    float th;
    asm("tanh.approx.f32 %0, %1;" : "=f"(th) : "f"(a));
    return th;
}

// ---------------- Phase 0a: vb = bias + 0.5 * sum_h V ----------------
__global__ __launch_bounds__(128) void nade_vb(
    const float* __restrict__ V, const float* __restrict__ bias)
{
    const int i = blockIdx.x * 128 + threadIdx.x;   // 0..4095
    float s = 0.f;
#pragma unroll 8
    for (int h = 0; h < HH; h++)
        s += __ldg(&V[(size_t)h * (DD * CC) + i]);
    g_VB[i] = fmaf(0.5f, s, __ldg(&bias[i]));
}

// ---------------- Phase 0b: xT[d][b] = 0.5 * x[b][d] ----------------
__global__ __launch_bounds__(256) void nade_xt(const float* __restrict__ x)
{
    __shared__ float tile[32][33];
    const int b0 = blockIdx.x * 32;
    const int d0 = blockIdx.y * 32;
    const int tx = threadIdx.x;       // 0..31
    const int ty = threadIdx.y;       // 0..7
#pragma unroll
    for (int r = 0; r < 4; r++)
        tile[ty + 8 * r][tx] = __ldg(&x[(size_t)(b0 + ty + 8 * r) * DD + d0 + tx]);
    __syncthreads();
#pragma unroll
    for (int r = 0; r < 4; r++)
        g_XT[(size_t)(d0 + ty + 8 * r) * BB + b0 + tx] = 0.5f * tile[tx][ty + 8 * r];
}

// ---------------- Phase 1: chunked prefix GEMM (halved) ----------------
// grid (HH/16, BB/32), block 128: bl = tid&31 (b), hg = tid>>5 -> 4 contiguous h.
__global__ __launch_bounds__(128) void nade_phase1(
    const float* __restrict__ W, const float* __restrict__ cvec)
{
    const int h0 = blockIdx.x * 16;
    const int b0 = blockIdx.y * 32;
    const int tid = threadIdx.x;
    const int bl = tid & 31;
    const int hg = tid >> 5;            // 0..3
    const int hbase = h0 + hg * 4;
    const int b = b0 + bl;

    float acc[4];
#pragma unroll
    for (int m = 0; m < 4; m++) acc[m] = 0.5f * __ldg(&cvec[hbase + m]);

    for (int k = 0; k < KK; k++) {
        float* Pk = g_P + (size_t)k * HH * BB;
#pragma unroll
        for (int m = 0; m < 4; m++)
            Pk[(size_t)(hbase + m) * BB + b] = acc[m];

        float xv[DCH];
#pragma unroll
        for (int j = 0; j < DCH; j++)
            xv[j] = __ldg(&g_XT[(size_t)(k * DCH + j) * BB + b]);   // coalesced

#pragma unroll
        for (int m = 0; m < 4; m++) {
            const float4* wr = (const float4*)(W + (size_t)(hbase + m) * DD) + k * 4;
#pragma unroll
            for (int q = 0; q < 4; q++) {
                float4 w = __ldg(&wr[q]);                            // warp-uniform
                acc[m] = fmaf(xv[4 * q + 0], w.x, acc[m]);
                acc[m] = fmaf(xv[4 * q + 1], w.y, acc[m]);
                acc[m] = fmaf(xv[4 * q + 2], w.z, acc[m]);
                acc[m] = fmaf(xv[4 * q + 3], w.w, acc[m]);
            }
        }
    }
}

// ---------------- Phase 2: per-chunk sequential NADE ----------------
// grid (KK, BB/64), block 128 = 4 warps: hseg = wid&1, bg = wid>>1.
// Each thread: one b, all 16 d of the chunk, 256 h.
__global__ __launch_bounds__(128, 4) void nade_phase2(
    const float* __restrict__ V, const float* __restrict__ W,
    float* __restrict__ out)
{
    __shared__ float ws[HH][DCH];          // 32 KB: W[h][d0:d0+16]
    __shared__ float red[DCH * CC][64];    // 16 KB

    const int k = blockIdx.x;
    const int b0 = blockIdx.y * 64;
    const int tid = threadIdx.x;
    const int bl = tid & 31;
    const int wid = tid >> 5;
    const int hseg = wid & 1;
    const int bg = wid >> 1;
    const int bloc = bg * 32 + bl;
    const int b = b0 + bloc;
    const int d0 = k * DCH;

    // stage W slice: 512 rows x 64B, 4 lanes per row
    for (int i = tid; i < HH * 4; i += 128) {
        const int hh = i >> 2, q = i & 3;
        float4 wv = __ldg((const float4*)(W + (size_t)hh * DD + d0) + q);
        *(float4*)&ws[hh][q * 4] = wv;
    }

    // preload 0.5*x[b, d0:d0+16] (coalesced from xT)
    float xv[DCH];
#pragma unroll
    for (int j = 0; j < DCH; j++)
        xv[j] = __ldg(&g_XT[(size_t)(d0 + j) * BB + b]);

    float acc[DCH][CC];
#pragma unroll
    for (int d = 0; d < DCH; d++)
#pragma unroll
        for (int c = 0; c < CC; c++) acc[d][c] = 0.f;

    __syncthreads();

    const int hstart = hseg * HITER;
    const float* Pp = g_P + ((size_t)k * HH + hstart) * BB + b;
    const float4* Vp = (const float4*)V + ((size_t)hstart * DD + d0);

    float a_next = __ldg(Pp);
    for (int it = 0; it < HITER; ++it) {
        float a = a_next;
        Pp += BB;
        a_next = __ldg(Pp);                       // pad row makes last read safe
        const float* wr = ws[hstart + it];
#pragma unroll
        for (int q = 0; q < 4; q++) {
            float4 w4 = *(const float4*)(wr + 4 * q);   // broadcast LDS.128
            float wq[4] = {w4.x, w4.y, w4.z, w4.w};
#pragma unroll
            for (int r = 0; r < 4; r++) {
                const int d = 4 * q + r;
                float4 v = __ldg(Vp + d);               // warp-uniform L2
                float th = tanh_fast(a);
                acc[d][0] = fmaf(th, v.x, acc[d][0]);
                acc[d][1] = fmaf(th, v.y, acc[d][1]);
                acc[d][2] = fmaf(th, v.z, acc[d][2]);
                acc[d][3] = fmaf(th, v.w, acc[d][3]);
                a = fmaf(xv[d], wq[r], a);              // halved-prefix advance
            }
        }
        Vp += DD;
    }

    if (hseg == 1) {
#pragma unroll
        for (int d = 0; d < DCH; d++)
#pragma unroll
            for (int c = 0; c < CC; c++)
                red[d * CC + c][bloc] = acc[d][c];
    }
    __syncthreads();

    if (hseg == 0) {
        float* yout = out + (size_t)b * (DD * CC) + (size_t)d0 * CC;
        float* pout = yout + (size_t)BB * DD * CC;
#pragma unroll
        for (int d = 0; d < DCH; d++) {
            const float4 vb = *(const float4*)&g_VB[(d0 + d) * CC];
            float l[4];
            l[0] = fmaf(0.5f, acc[d][0] + red[d * CC + 0][bloc], vb.x);
            l[1] = fmaf(0.5f, acc[d][1] + red[d * CC + 1][bloc], vb.y);
            l[2] = fmaf(0.5f, acc[d][2] + red[d * CC + 2][bloc], vb.z);
            l[3] = fmaf(0.5f, acc[d][3] + red[d * CC + 3][bloc], vb.w);

            *(float4*)(yout + d * CC) = make_float4(l[0], l[1], l[2], l[3]);

            float m = fmaxf(fmaxf(l[0], l[1]), fmaxf(l[2], l[3]));
            float s = __expf(l[0] - m) + __expf(l[1] - m) +
                      __expf(l[2] - m) + __expf(l[3] - m);
            float lse = m + __logf(s);
            *(float4*)(pout + d * CC) =
                make_float4(l[0] - lse, l[1] - lse, l[2] - lse, l[3] - lse);
        }
    }
}

extern "C" void kernel_launch(void* const* d_in, const int* in_sizes, int n_in,
                              void* d_out, int out_size) {
    const float* x    = (const float*)d_in[0];
    const float* V    = (const float*)d_in[1];
    const float* bias = (const float*)d_in[2];
    const float* W    = (const float*)d_in[3];
    const float* cvec = (const float*)d_in[4];
    float* out = (float*)d_out;

    nade_vb<<<(DD * CC) / 128, 128>>>(V, bias);
    nade_xt<<<dim3(BB / 32, DD / 32), dim3(32, 8)>>>(x);
    nade_phase1<<<dim3(HH / 16, BB / 32), 128>>>(W, cvec);
    nade_phase2<<<dim3(KK, BB / 64), 128>>>(V, W, out);
}